// round 15
// baseline (speedup 1.0000x reference)
#include <cuda_runtime.h>
#include <cstdint>

typedef unsigned long long ull;

// Packed f32x2 FMA — only reachable via PTX (ptxas never auto-fuses 2x fmaf).
#define FMA2(d, a, b, c) \
    asm("fma.rn.f32x2 %0, %1, %2, %3;" : "=l"(d) : "l"(a), "l"(b), "l"(c))

__device__ __forceinline__ ull pack2(float lo, float hi) {
    ull r;
    asm("mov.b64 %0, {%1, %2};" : "=l"(r) : "f"(lo), "f"(hi));
    return r;
}

namespace {
constexpr int H  = 224;
constexpr int W  = 224;
constexpr int HO = 222;
constexpr int WO = 222;
constexpr int OC = 64;
constexpr int TPB = 224;   // 2 rows x 112 pair-slots (111 active: 99.1% lanes)
}

// R12 body EXACTLY (measured best, 70.7us). Single delta: launch_bounds
// min-blocks 5 -> 6 (reg cap 54 -> 48, theoretical occ 54.7% -> 65.6%).
// Free gamble: if ptxas fits 48 regs we gain latency hiding; if it spills,
// R12 remains the banked best.
__global__ __launch_bounds__(TPB, 6)
void Conv2d_68298569941797_kernel(const float* __restrict__ data,
                                  const float* __restrict__ weight,
                                  float* __restrict__ out) {
    __shared__ float s_in[4 * W];          // input rows y0..y0+3
    __shared__ ull   s_w[OC * 10];         // 9 packed (w,w) + pad -> LDS.128-friendly

    const int tid = threadIdx.x;
    const int b   = blockIdx.y;
    const int y0  = blockIdx.x * 2;

    // Stage 4 input rows (y0 <= 220 -> rows <= 223, in bounds).
    const float* src = data + ((size_t)b * H + y0) * W;
    for (int i = tid; i < 4 * W; i += TPB) s_in[i] = src[i];

    // Stage weights, duplicated into both f32x2 lanes.
    for (int i = tid; i < OC * 9; i += TPB) {
        int o = i / 9;
        int k = i - o * 9;
        float w = weight[i];
        s_w[o * 10 + k] = pack2(w, w);
    }
    __syncthreads();

    const int r = tid / 112;          // output row within block
    const int s = tid - r * 112;      // pair slot
    if (s >= 111) return;             // 111 pairs cover WO=222 exactly
    const int x = 2 * s;

    // 9 packed sliding-pair operands: rows r..r+2, cols x..x+3.
    const float* rowp = s_in + r * W + x;
    ull P[9];
#pragma unroll
    for (int rr = 0; rr < 3; ++rr) {
        float a0 = rowp[rr * W + 0];
        float a1 = rowp[rr * W + 1];
        float a2 = rowp[rr * W + 2];
        float a3 = rowp[rr * W + 3];
        P[rr * 3 + 0] = pack2(a0, a1);
        P[rr * 3 + 1] = pack2(a1, a2);
        P[rr * 3 + 2] = pack2(a2, a3);
    }

    const size_t plane = (size_t)HO * WO;
    float* op = out + (((size_t)b * OC) * HO + (y0 + r)) * WO + x;
    const ulonglong2* w2 = reinterpret_cast<const ulonglong2*>(s_w);

#pragma unroll 2
    for (int o = 0; o < OC; ++o) {
        const ulonglong2* wo = w2 + o * 5;
        ulonglong2 w01 = wo[0];
        ulonglong2 w23 = wo[1];
        ulonglong2 w45 = wo[2];
        ulonglong2 w67 = wo[3];
        ulonglong2 w8x = wo[4];   // .y is padding, never used

        ull acc = 0ull;           // packed (0.0f, 0.0f)
        FMA2(acc, P[0], w01.x, acc);
        FMA2(acc, P[1], w01.y, acc);
        FMA2(acc, P[2], w23.x, acc);
        FMA2(acc, P[3], w23.y, acc);
        FMA2(acc, P[4], w45.x, acc);
        FMA2(acc, P[5], w45.y, acc);
        FMA2(acc, P[6], w67.x, acc);
        FMA2(acc, P[7], w67.y, acc);
        FMA2(acc, P[8], w8x.x, acc);

        *reinterpret_cast<ull*>(op) = acc;  // STG.64, 8B-aligned, coalesced
        op += plane;
    }
}

extern "C" void kernel_launch(void* const* d_in, const int* in_sizes, int n_in,
                              void* d_out, int out_size) {
    const float* data   = (const float*)d_in[0];
    const float* weight = (const float*)d_in[1];
    float* out          = (float*)d_out;

    dim3 grid(HO / 2, 32);   // (111, 32)
    Conv2d_68298569941797_kernel<<<grid, TPB>>>(data, weight, out);
}

// round 16
// speedup vs baseline: 1.4139x; 1.4139x over previous
#include <cuda_runtime.h>
#include <cstdint>

typedef unsigned long long ull;

// Packed f32x2 FMA — only reachable via PTX (ptxas never auto-fuses 2x fmaf).
#define FMA2(d, a, b, c) \
    asm("fma.rn.f32x2 %0, %1, %2, %3;" : "=l"(d) : "l"(a), "l"(b), "l"(c))

__device__ __forceinline__ ull pack2(float lo, float hi) {
    ull r;
    asm("mov.b64 %0, {%1, %2};" : "=l"(r) : "f"(lo), "f"(hi));
    return r;
}

namespace {
constexpr int H  = 224;
constexpr int W  = 224;
constexpr int HO = 222;
constexpr int WO = 222;
constexpr int OC = 64;
constexpr int TPB = 224;   // 2 rows x 112 pair-slots (111 active: 99.1% lanes)
}

// FINAL (R12, measured best 70.7us): block = 2 output rows x 222 cols x 64 ch,
// thread = 1 row x 2 cols x 64 channels, packed-f32x2 math, smem weights
// (broadcast LDS.128), STG.64 coalesced stores, launch_bounds(224,5).
// Verified negatives: unroll4 (-), float4 staging (0), min-blocks 6 (spill, -),
// bigger tiles (-), register-weight strips (-), contiguous-region blocks (-).
__global__ __launch_bounds__(TPB, 5)
void Conv2d_68298569941797_kernel(const float* __restrict__ data,
                                  const float* __restrict__ weight,
                                  float* __restrict__ out) {
    __shared__ float s_in[4 * W];          // input rows y0..y0+3
    __shared__ ull   s_w[OC * 10];         // 9 packed (w,w) + pad -> LDS.128-friendly

    const int tid = threadIdx.x;
    const int b   = blockIdx.y;
    const int y0  = blockIdx.x * 2;

    // Stage 4 input rows (y0 <= 220 -> rows <= 223, in bounds).
    const float* src = data + ((size_t)b * H + y0) * W;
    for (int i = tid; i < 4 * W; i += TPB) s_in[i] = src[i];

    // Stage weights, duplicated into both f32x2 lanes.
    for (int i = tid; i < OC * 9; i += TPB) {
        int o = i / 9;
        int k = i - o * 9;
        float w = weight[i];
        s_w[o * 10 + k] = pack2(w, w);
    }
    __syncthreads();

    const int r = tid / 112;          // output row within block
    const int s = tid - r * 112;      // pair slot
    if (s >= 111) return;             // 111 pairs cover WO=222 exactly
    const int x = 2 * s;

    // 9 packed sliding-pair operands: rows r..r+2, cols x..x+3.
    const float* rowp = s_in + r * W + x;
    ull P[9];
#pragma unroll
    for (int rr = 0; rr < 3; ++rr) {
        float a0 = rowp[rr * W + 0];
        float a1 = rowp[rr * W + 1];
        float a2 = rowp[rr * W + 2];
        float a3 = rowp[rr * W + 3];
        P[rr * 3 + 0] = pack2(a0, a1);
        P[rr * 3 + 1] = pack2(a1, a2);
        P[rr * 3 + 2] = pack2(a2, a3);
    }

    const size_t plane = (size_t)HO * WO;
    float* op = out + (((size_t)b * OC) * HO + (y0 + r)) * WO + x;
    const ulonglong2* w2 = reinterpret_cast<const ulonglong2*>(s_w);

#pragma unroll 2
    for (int o = 0; o < OC; ++o) {
        const ulonglong2* wo = w2 + o * 5;
        ulonglong2 w01 = wo[0];
        ulonglong2 w23 = wo[1];
        ulonglong2 w45 = wo[2];
        ulonglong2 w67 = wo[3];
        ulonglong2 w8x = wo[4];   // .y is padding, never used

        ull acc = 0ull;           // packed (0.0f, 0.0f)
        FMA2(acc, P[0], w01.x, acc);
        FMA2(acc, P[1], w01.y, acc);
        FMA2(acc, P[2], w23.x, acc);
        FMA2(acc, P[3], w23.y, acc);
        FMA2(acc, P[4], w45.x, acc);
        FMA2(acc, P[5], w45.y, acc);
        FMA2(acc, P[6], w67.x, acc);
        FMA2(acc, P[7], w67.y, acc);
        FMA2(acc, P[8], w8x.x, acc);

        *reinterpret_cast<ull*>(op) = acc;  // STG.64, 8B-aligned, coalesced
        op += plane;
    }
}

extern "C" void kernel_launch(void* const* d_in, const int* in_sizes, int n_in,
                              void* d_out, int out_size) {
    const float* data   = (const float*)d_in[0];
    const float* weight = (const float*)d_in[1];
    float* out          = (float*)d_out;

    dim3 grid(HO / 2, 32);   // (111, 32)
    Conv2d_68298569941797_kernel<<<grid, TPB>>>(data, weight, out);
}